// round 3
// baseline (speedup 1.0000x reference)
#include <cuda_runtime.h>
#include <math.h>

#define NE 16          // experts
#define NPTS 524288
#define ESTRIDE 37     // odd stride -> conflict-free expert-indexed shared loads

// Fused per-expert 7x4 matrix: rows = [rho, phi, theta, cos_t, sin_t, silu(cos_t), silu(sin_t)]
__device__ float g_M[NE * 28];

// ---------------------------------------------------------------------------
// Fold kernel: M_e[i][j] for i<3  = sum_p proj[e,i,p] * (W1[e,p,:] . Wf[e,:,j])
//              M_e[3+q][j]        = (W1[e,8+q,:] . Wf[e,:,j])
// 16 experts * 28 elements = 448 threads, one block. Tiny; recomputed per call.
// ---------------------------------------------------------------------------
__global__ void fold_kernel(const float* __restrict__ proj,   // (E,3,8)
                            const float* __restrict__ W1,     // (E,12,32)
                            const float* __restrict__ Wf)     // (E,32,4)
{
    int tid = threadIdx.x;
    if (tid >= NE * 28) return;
    int e = tid / 28;
    int r = tid - e * 28;
    int i = r >> 2;      // 0..6
    int j = r & 3;       // 0..3
    const float* W1e = W1 + e * 12 * 32;
    const float* Wfe = Wf + e * 32 * 4;
    float acc = 0.f;
    if (i < 3) {
        const float* pe = proj + e * 24 + i * 8;
        #pragma unroll
        for (int p = 0; p < 8; ++p) {
            float f = 0.f;
            #pragma unroll
            for (int h = 0; h < 32; ++h)
                f += W1e[p * 32 + h] * Wfe[h * 4 + j];
            acc += pe[p] * f;
        }
    } else {
        int q = 8 + (i - 3);
        #pragma unroll
        for (int h = 0; h < 32; ++h)
            acc += W1e[q * 32 + h] * Wfe[h * 4 + j];
    }
    g_M[e * 28 + i * 4 + j] = acc;
}

// ---------------------------------------------------------------------------
// Main kernel: 1 point per thread.
// ---------------------------------------------------------------------------
__device__ __forceinline__ float fast_sig(float x)
{
    return __fdividef(1.f, 1.f + __expf(-x));
}

__global__ __launch_bounds__(256)
void moe_kernel(const float4* __restrict__ xyzt,
                const float*  __restrict__ Wg,      // (4,16)
                const float*  __restrict__ bg,      // (16)
                const float*  __restrict__ center,  // (16,3)
                const float*  __restrict__ tb1,     // (16)
                const float*  __restrict__ tb2,     // (16)
                const float*  __restrict__ bf,      // (16,4)
                float4*       __restrict__ out)
{
    __shared__ float sWg[64];
    __shared__ float sbg[16];
    __shared__ float sE[NE * ESTRIDE];
    // per-expert layout: [0..2]=center, [3]=tb1, [4]=tb2, [5..32]=M(7x4), [33..36]=bf

    int t = threadIdx.x;
    if (t < 64) sWg[t] = Wg[t];
    if (t < 16) sbg[t] = bg[t];
    for (int idx = t; idx < NE * ESTRIDE; idx += blockDim.x) {
        int e = idx / ESTRIDE;
        int o = idx - e * ESTRIDE;
        float v;
        if (o < 3)       v = center[e * 3 + o];
        else if (o == 3) v = tb1[e];
        else if (o == 4) v = tb2[e];
        else if (o < 33) v = g_M[e * 28 + (o - 5)];
        else             v = bf[e * 4 + (o - 33)];
        sE[idx] = v;
    }
    __syncthreads();

    int i = blockIdx.x * blockDim.x + t;
    if (i >= NPTS) return;
    float4 p = xyzt[i];

    // gating: logits = xyzt @ Wg + bg ; track top-2
    float best0 = -1e30f, best1 = -1e30f;
    int e0 = 0, e1 = 0;
    #pragma unroll
    for (int e = 0; e < NE; ++e) {
        float l = sbg[e] + p.x * sWg[e] + p.y * sWg[16 + e]
                         + p.z * sWg[32 + e] + p.w * sWg[48 + e];
        if (l > best0) { best1 = best0; e1 = e0; best0 = l; e0 = e; }
        else if (l > best1) { best1 = l; e1 = e; }
    }
    // softmax over the top-2 = sigmoid of the difference
    float w0 = fast_sig(best0 - best1);
    float w1 = 1.f - w0;

    float o0 = 0.f, o1 = 0.f, o2 = 0.f, o3 = 0.f;

    #pragma unroll
    for (int k = 0; k < 2; ++k) {
        int   e = k ? e1 : e0;
        float w = k ? w1 : w0;
        const float* q = sE + e * ESTRIDE;

        float xc0 = p.x - q[0];
        float xc1 = p.y - q[1];
        float xc2 = p.z - q[2];
        float r2  = xc0 * xc0 + xc1 * xc1 + xc2 * xc2;
        float rho = sqrtf(r2);
        float phi = atan2f(xc1, xc0);
        // accurate division + clamp: acos derivative blows up near |arg|=1
        float ca = xc2 / (rho + 1e-6f);
        ca = fminf(1.f, fmaxf(-1.f, ca));
        float theta = acosf(ca);

        float ct = __cosf(p.w + q[3]);
        float st = __sinf(p.w + q[4]);
        float sc = ct * fast_sig(ct);
        float ss = st * fast_sig(st);

        float f0 = rho, f1 = phi, f2 = theta, f3 = ct, f4 = st, f5 = sc, f6 = ss;

        #pragma unroll
        for (int j = 0; j < 4; ++j) {
            float a = q[33 + j];
            a += f0 * q[5 +  0 + j];
            a += f1 * q[5 +  4 + j];
            a += f2 * q[5 +  8 + j];
            a += f3 * q[5 + 12 + j];
            a += f4 * q[5 + 16 + j];
            a += f5 * q[5 + 20 + j];
            a += f6 * q[5 + 24 + j];
            a *= w;
            if (j == 0) o0 += a; else if (j == 1) o1 += a;
            else if (j == 2) o2 += a; else o3 += a;
        }
    }

    out[i] = make_float4(o0, o1, o2, o3);
}

// ---------------------------------------------------------------------------
extern "C" void kernel_launch(void* const* d_in, const int* in_sizes, int n_in,
                              void* d_out, int out_size)
{
    const float*  xyzt   = (const float*)d_in[0];
    const float*  Wg     = (const float*)d_in[1];
    const float*  bg     = (const float*)d_in[2];
    const float*  proj   = (const float*)d_in[3];
    const float*  center = (const float*)d_in[4];
    const float*  tb1    = (const float*)d_in[5];
    const float*  tb2    = (const float*)d_in[6];
    const float*  W1     = (const float*)d_in[7];
    const float*  Wf     = (const float*)d_in[8];
    const float*  bf     = (const float*)d_in[9];
    float* out = (float*)d_out;

    fold_kernel<<<1, 448>>>(proj, W1, Wf);

    int threads = 256;
    int blocks  = NPTS / threads;   // 524288 / 256 = 2048, exact
    moe_kernel<<<blocks, threads>>>((const float4*)xyzt, Wg, bg, center,
                                    tb1, tb2, bf, (float4*)out);
}

// round 4
// speedup vs baseline: 1.0694x; 1.0694x over previous
#include <cuda_runtime.h>
#include <math.h>

#define NE 16
#define NPTS 524288

// Final packed parameter blob, in the exact layout the main kernel's shared
// memory uses (784 floats = 196 float4):
//   [0..63]   gate weights transposed: gate[e] = {Wg[0][e],Wg[1][e],Wg[2][e],Wg[3][e]}
//   [64..79]  bg
//   [80 + e*44 + ...] expert record e (stride 44 floats = 11 float4):
//       [0..3]  = cx, cy, cz, tb1
//       [4]     = tb2            ([5..7] pad)
//       [8..39] = M (8 rows x 4): rows = rho, phi, theta, cos, sin,
//                                  silu(cos), silu(sin), bias(bf)
//       [40..43] pad
__device__ float4 g_R4[196];

// ---------------------------------------------------------------------------
// Fold kernel (one block, 768 threads):
// Stage 1: P[e][p][j] = W1[e,p,:] . Wf[e,:,j]   (16*12*4 = 768 dots of len 32)
// Stage 2: assemble g_R4 blob (folding proj into the first 3 M rows).
// ---------------------------------------------------------------------------
__global__ void fold_kernel(const float* __restrict__ proj,    // (E,3,8)
                            const float* __restrict__ center,  // (E,3)
                            const float* __restrict__ tb1,     // (E)
                            const float* __restrict__ tb2,     // (E)
                            const float* __restrict__ W1,      // (E,12,32)
                            const float* __restrict__ Wf,      // (E,32,4)
                            const float* __restrict__ bf,      // (E,4)
                            const float* __restrict__ Wg,      // (4,16)
                            const float* __restrict__ bg)      // (16)
{
    __shared__ float P[NE * 12 * 4];
    int tid = threadIdx.x;          // 768 threads
    {
        int e = tid / 48, r = tid - e * 48;
        int pi = r >> 2, j = r & 3;
        const float* W1r = W1 + (e * 12 + pi) * 32;
        const float* Wfe = Wf + e * 128 + j;
        float acc = 0.f;
        #pragma unroll
        for (int h = 0; h < 32; ++h) acc = fmaf(W1r[h], Wfe[h * 4], acc);
        P[tid] = acc;               // tid == e*48 + pi*4 + j
    }
    __syncthreads();

    float* gR = (float*)g_R4;
    for (int idx = tid; idx < 784; idx += 768) {
        float v = 0.f;
        if (idx < 64) {
            int e = idx >> 2, c = idx & 3;
            v = Wg[c * 16 + e];
        } else if (idx < 80) {
            v = bg[idx - 64];
        } else {
            int rr = idx - 80;
            int e = rr / 44, o = rr - e * 44;
            if (o < 3)        v = center[e * 3 + o];
            else if (o == 3)  v = tb1[e];
            else if (o == 4)  v = tb2[e];
            else if (o >= 8 && o < 40) {
                int m = o - 8, i = m >> 2, j = m & 3;
                if (i < 3) {                        // rho/phi/theta rows: proj fold
                    const float* pe = proj + e * 24 + i * 8;
                    const float* Pe = P + e * 48;
                    float acc = 0.f;
                    #pragma unroll
                    for (int p = 0; p < 8; ++p)
                        acc = fmaf(pe[p], Pe[p * 4 + j], acc);
                    v = acc;
                } else if (i < 7) {                  // temb rows
                    v = P[e * 48 + (8 + i - 3) * 4 + j];
                } else {                             // bias row
                    v = bf[e * 4 + j];
                }
            }
            // o in {5,6,7,40..43}: pad = 0
        }
        gR[idx] = v;
    }
}

// ---------------------------------------------------------------------------
// Main kernel helpers
// ---------------------------------------------------------------------------
__device__ __forceinline__ float fast_sig(float x)
{
    return __fdividef(1.f, 1.f + __expf(-x));
}

// Branch-free atan2, abs err ~1e-5. Also used for theta = atan2(rxy, z) = acos(z/rho).
__device__ __forceinline__ float atan2f_fast(float y, float x)
{
    float ax = fabsf(x), ay = fabsf(y);
    float mx = fmaxf(ax, ay);
    float mn = fminf(ax, ay);
    float a  = __fdividef(mn, mx);
    float s  = a * a;
    float r  = fmaf(s, -0.0117212f, 0.05265332f);
    r = fmaf(s, r, -0.11643287f);
    r = fmaf(s, r,  0.19354346f);
    r = fmaf(s, r, -0.33262347f);
    r = fmaf(s, r,  0.99997726f);
    r = r * a;
    r = (ay > ax)  ? 1.57079632679f - r : r;
    r = (x < 0.f)  ? 3.14159265359f - r : r;
    return copysignf(r, y);
}

// ---------------------------------------------------------------------------
// Main kernel: 1 point per thread, all params pre-packed in g_R4.
// ---------------------------------------------------------------------------
__global__ __launch_bounds__(256)
void moe_kernel(const float4* __restrict__ xyzt, float4* __restrict__ out)
{
    __shared__ float4 sBuf[196];
    int t = threadIdx.x;
    if (t < 196) sBuf[t] = g_R4[t];
    __syncthreads();

    const float*  sF   = (const float*)sBuf;
    const float4* gate = sBuf;          // 16 x float4
    const float*  sbg  = sF + 64;       // 16

    int i = blockIdx.x * 256 + t;
    float4 p = xyzt[i];

    // gating: top-2 of 16 logits
    float best0 = -1e30f, best1 = -1e30f;
    int e0 = 0, e1 = 0;
    #pragma unroll
    for (int e = 0; e < NE; ++e) {
        float4 g = gate[e];
        float l = fmaf(p.x, g.x, fmaf(p.y, g.y, fmaf(p.z, g.z, fmaf(p.w, g.w, sbg[e]))));
        bool gt0 = l > best0;
        bool gt1 = l > best1;
        best1 = gt0 ? best0 : (gt1 ? l : best1);
        e1    = gt0 ? e0    : (gt1 ? e : e1);
        best0 = gt0 ? l : best0;
        e0    = gt0 ? e : e0;
    }
    float w0 = fast_sig(best0 - best1);   // softmax over 2 = sigmoid(diff)
    float w1 = 1.f - w0;

    float4 o = make_float4(0.f, 0.f, 0.f, 0.f);

    #pragma unroll
    for (int k = 0; k < 2; ++k) {
        int   e = k ? e1 : e0;
        float w = k ? w1 : w0;
        const float4* R = sBuf + 20 + e * 11;   // 20 f4 = 80-float header

        float4 A   = R[0];                      // cx, cy, cz, tb1
        float tb2v = R[1].x;

        float xc0 = p.x - A.x;
        float xc1 = p.y - A.y;
        float xc2 = p.z - A.z;
        float r2xy = fmaf(xc0, xc0, xc1 * xc1);
        float rxy  = sqrtf(r2xy);
        float rho  = sqrtf(fmaf(xc2, xc2, r2xy));
        float phi   = atan2f_fast(xc1, xc0);
        float theta = atan2f_fast(rxy, xc2);    // == acos(z/rho)

        float ct = __cosf(p.w + A.w);
        float st = __sinf(p.w + tb2v);
        float sc = ct * fast_sig(ct);
        float ss = st * fast_sig(st);

        float4 v = R[9];                        // bias row (bf)
        float4 m;
        m = R[2]; v.x = fmaf(rho,   m.x, v.x); v.y = fmaf(rho,   m.y, v.y); v.z = fmaf(rho,   m.z, v.z); v.w = fmaf(rho,   m.w, v.w);
        m = R[3]; v.x = fmaf(phi,   m.x, v.x); v.y = fmaf(phi,   m.y, v.y); v.z = fmaf(phi,   m.z, v.z); v.w = fmaf(phi,   m.w, v.w);
        m = R[4]; v.x = fmaf(theta, m.x, v.x); v.y = fmaf(theta, m.y, v.y); v.z = fmaf(theta, m.z, v.z); v.w = fmaf(theta, m.w, v.w);
        m = R[5]; v.x = fmaf(ct,    m.x, v.x); v.y = fmaf(ct,    m.y, v.y); v.z = fmaf(ct,    m.z, v.z); v.w = fmaf(ct,    m.w, v.w);
        m = R[6]; v.x = fmaf(st,    m.x, v.x); v.y = fmaf(st,    m.y, v.y); v.z = fmaf(st,    m.z, v.z); v.w = fmaf(st,    m.w, v.w);
        m = R[7]; v.x = fmaf(sc,    m.x, v.x); v.y = fmaf(sc,    m.y, v.y); v.z = fmaf(sc,    m.z, v.z); v.w = fmaf(sc,    m.w, v.w);
        m = R[8]; v.x = fmaf(ss,    m.x, v.x); v.y = fmaf(ss,    m.y, v.y); v.z = fmaf(ss,    m.z, v.z); v.w = fmaf(ss,    m.w, v.w);

        o.x = fmaf(w, v.x, o.x);
        o.y = fmaf(w, v.y, o.y);
        o.z = fmaf(w, v.z, o.z);
        o.w = fmaf(w, v.w, o.w);
    }

    out[i] = o;
}

// ---------------------------------------------------------------------------
extern "C" void kernel_launch(void* const* d_in, const int* in_sizes, int n_in,
                              void* d_out, int out_size)
{
    const float* xyzt   = (const float*)d_in[0];
    const float* Wg     = (const float*)d_in[1];
    const float* bg     = (const float*)d_in[2];
    const float* proj   = (const float*)d_in[3];
    const float* center = (const float*)d_in[4];
    const float* tb1    = (const float*)d_in[5];
    const float* tb2    = (const float*)d_in[6];
    const float* W1     = (const float*)d_in[7];
    const float* Wf     = (const float*)d_in[8];
    const float* bf     = (const float*)d_in[9];
    float* out = (float*)d_out;

    fold_kernel<<<1, 768>>>(proj, center, tb1, tb2, W1, Wf, bf, Wg, bg);

    moe_kernel<<<NPTS / 256, 256>>>((const float4*)xyzt, (float4*)out);
}

// round 5
// speedup vs baseline: 1.2419x; 1.1613x over previous
#include <cuda_runtime.h>
#include <math.h>

#define NE     16
#define NPTS   524288
#define TPB    512
#define PPT    4
#define NBLK   (NPTS / (TPB * PPT))   // 256

// ---------------------------------------------------------------------------
// helpers
// ---------------------------------------------------------------------------
__device__ __forceinline__ float fast_sig(float x)
{
    return __fdividef(1.f, 1.f + __expf(-x));
}

// Branch-free atan2, abs err ~1e-5. theta = atan2(rxy, z) == acos(z/rho).
__device__ __forceinline__ float atan2f_fast(float y, float x)
{
    float ax = fabsf(x), ay = fabsf(y);
    float mx = fmaxf(ax, ay);
    float mn = fminf(ax, ay);
    float a  = __fdividef(mn, mx);
    float s  = a * a;
    float r  = fmaf(s, -0.0117212f, 0.05265332f);
    r = fmaf(s, r, -0.11643287f);
    r = fmaf(s, r,  0.19354346f);
    r = fmaf(s, r, -0.33262347f);
    r = fmaf(s, r,  0.99997726f);
    r = r * a;
    r = (ay > ax) ? 1.57079632679f - r : r;
    r = (x < 0.f) ? 3.14159265359f - r : r;
    return copysignf(r, y);
}

// ---------------------------------------------------------------------------
// One fused kernel. Each block folds the tiny MoE weights into a packed blob
// in its own shared memory (redundantly, ~1us one-time), then streams points.
//
// Blob layout (float4 units):
//   sBlob[0..15]   gate[e] = {Wg[0][e],Wg[1][e],Wg[2][e],Wg[3][e]}
//   sBlob[16..19]  bg (16 floats)
//   sBlob[20+e*11 + r], r = 0: (cx,cy,cz,tb1)
//                       r = 1: (tb2,-,-,-)
//                       r = 2..8: M rows rho,phi,theta,cos,sin,silu(cos),silu(sin)
//                       r = 9: bias (bf[e])
//                       r = 10: pad
// ---------------------------------------------------------------------------
__global__ __launch_bounds__(TPB, 2)
void moe_fused_kernel(const float4* __restrict__ xyzt,
                      const float*  __restrict__ Wg,
                      const float*  __restrict__ bg,
                      const float*  __restrict__ proj,
                      const float*  __restrict__ center,
                      const float*  __restrict__ tb1,
                      const float*  __restrict__ tb2,
                      const float*  __restrict__ W1,
                      const float*  __restrict__ Wf,
                      const float*  __restrict__ bf,
                      float4*       __restrict__ out)
{
    __shared__ float4 sWf4[NE * 32];   // Wf rows as float4 (E,32,4)
    __shared__ float  sProj[NE * 24];  // (E,3,8)
    __shared__ float4 sP4[NE * 12];    // P[e][p][0..3] = W1 row . Wf cols
    __shared__ float4 sBlob[196];

    const int t = threadIdx.x;

    // --- stage A: stage Wf + proj into smem (coalesced) ---
    sWf4[t] = ((const float4*)Wf)[t];                 // 512 float4 exactly
    if (t < 96) ((float4*)sProj)[t] = ((const float4*)proj)[t];
    __syncthreads();

    // --- stage B: P[e,p,:] = W1[e,p,:] @ Wf[e]  (192 dots of length 32) ---
    if (t < NE * 12) {
        int e = t / 12;
        const float4* w1r = (const float4*)(W1 + t * 32);
        const float4* wfe = sWf4 + e * 32;
        float4 acc = make_float4(0.f, 0.f, 0.f, 0.f);
        #pragma unroll
        for (int hh = 0; hh < 8; ++hh) {
            float4 a = w1r[hh];
            float4 b;
            b = wfe[hh*4+0]; acc.x=fmaf(a.x,b.x,acc.x); acc.y=fmaf(a.x,b.y,acc.y); acc.z=fmaf(a.x,b.z,acc.z); acc.w=fmaf(a.x,b.w,acc.w);
            b = wfe[hh*4+1]; acc.x=fmaf(a.y,b.x,acc.x); acc.y=fmaf(a.y,b.y,acc.y); acc.z=fmaf(a.y,b.z,acc.z); acc.w=fmaf(a.y,b.w,acc.w);
            b = wfe[hh*4+2]; acc.x=fmaf(a.z,b.x,acc.x); acc.y=fmaf(a.z,b.y,acc.y); acc.z=fmaf(a.z,b.z,acc.z); acc.w=fmaf(a.z,b.w,acc.w);
            b = wfe[hh*4+3]; acc.x=fmaf(a.w,b.x,acc.x); acc.y=fmaf(a.w,b.y,acc.y); acc.z=fmaf(a.w,b.z,acc.z); acc.w=fmaf(a.w,b.w,acc.w);
        }
        sP4[t] = acc;
    }
    __syncthreads();

    // --- stage C: assemble blob (16 threads, one per expert) ---
    if (t < NE) {
        int e = t;
        sBlob[e] = make_float4(Wg[e], Wg[16+e], Wg[32+e], Wg[48+e]);
        ((float*)(sBlob + 16))[e] = bg[e];
        float4* R = sBlob + 20 + e * 11;
        R[0] = make_float4(center[e*3], center[e*3+1], center[e*3+2], tb1[e]);
        R[1] = make_float4(tb2[e], 0.f, 0.f, 0.f);
        #pragma unroll
        for (int i = 0; i < 3; ++i) {           // fold proj into rho/phi/theta rows
            float4 acc = make_float4(0.f, 0.f, 0.f, 0.f);
            const float* pe = sProj + e*24 + i*8;
            #pragma unroll
            for (int p = 0; p < 8; ++p) {
                float4 b = sP4[e*12 + p];
                float  s = pe[p];
                acc.x=fmaf(s,b.x,acc.x); acc.y=fmaf(s,b.y,acc.y);
                acc.z=fmaf(s,b.z,acc.z); acc.w=fmaf(s,b.w,acc.w);
            }
            R[2 + i] = acc;
        }
        #pragma unroll
        for (int m = 0; m < 4; ++m)             // temb rows
            R[5 + m] = sP4[e*12 + 8 + m];
        R[9] = ((const float4*)bf)[e];          // bias row
    }
    __syncthreads();

    // --- stage D: stream points, 4 per thread ---
    const float4* gate = sBlob;
    const float*  sbg  = (const float*)(sBlob + 16);
    const int base = blockIdx.x * (TPB * PPT) + t;

    float4 pt[PPT];
    #pragma unroll
    for (int pp = 0; pp < PPT; ++pp) pt[pp] = xyzt[base + pp * TPB];

    #pragma unroll
    for (int pp = 0; pp < PPT; ++pp) {
        float4 p = pt[pp];

        // gating: top-2 of 16 via FMNMX chain, expert index in low 4 mantissa bits
        float b0 = -3.0e38f, b1 = -3.0e38f;
        #pragma unroll
        for (int e = 0; e < NE; ++e) {
            float4 g = gate[e];
            float l = fmaf(p.x, g.x, fmaf(p.y, g.y, fmaf(p.z, g.z, fmaf(p.w, g.w, sbg[e]))));
            l = __int_as_float((__float_as_int(l) & 0xFFFFFFF0) | e);
            b1 = fmaxf(b1, fminf(b0, l));
            b0 = fmaxf(b0, l);
        }
        int e0 = __float_as_int(b0) & 15;
        int e1 = __float_as_int(b1) & 15;
        float w0 = fast_sig(b0 - b1);           // softmax over 2 = sigmoid(diff)
        float w1 = 1.f - w0;

        float4 o = make_float4(0.f, 0.f, 0.f, 0.f);

        #pragma unroll
        for (int k = 0; k < 2; ++k) {
            int   e = k ? e1 : e0;
            float w = k ? w1 : w0;
            const float4* R = sBlob + 20 + e * 11;

            float4 A   = R[0];
            float tb2v = R[1].x;

            float xc0 = p.x - A.x;
            float xc1 = p.y - A.y;
            float xc2 = p.z - A.z;
            float r2xy = fmaf(xc0, xc0, xc1 * xc1);
            float rxy  = sqrtf(r2xy);
            float rho  = sqrtf(fmaf(xc2, xc2, r2xy));
            float phi   = atan2f_fast(xc1, xc0);
            float theta = atan2f_fast(rxy, xc2);

            float ct = __cosf(p.w + A.w);
            float st = __sinf(p.w + tb2v);
            float sc = ct * fast_sig(ct);
            float ss = st * fast_sig(st);

            float4 v = R[9];
            float4 m;
            m = R[2]; v.x=fmaf(rho,  m.x,v.x); v.y=fmaf(rho,  m.y,v.y); v.z=fmaf(rho,  m.z,v.z); v.w=fmaf(rho,  m.w,v.w);
            m = R[3]; v.x=fmaf(phi,  m.x,v.x); v.y=fmaf(phi,  m.y,v.y); v.z=fmaf(phi,  m.z,v.z); v.w=fmaf(phi,  m.w,v.w);
            m = R[4]; v.x=fmaf(theta,m.x,v.x); v.y=fmaf(theta,m.y,v.y); v.z=fmaf(theta,m.z,v.z); v.w=fmaf(theta,m.w,v.w);
            m = R[5]; v.x=fmaf(ct,   m.x,v.x); v.y=fmaf(ct,   m.y,v.y); v.z=fmaf(ct,   m.z,v.z); v.w=fmaf(ct,   m.w,v.w);
            m = R[6]; v.x=fmaf(st,   m.x,v.x); v.y=fmaf(st,   m.y,v.y); v.z=fmaf(st,   m.z,v.z); v.w=fmaf(st,   m.w,v.w);
            m = R[7]; v.x=fmaf(sc,   m.x,v.x); v.y=fmaf(sc,   m.y,v.y); v.z=fmaf(sc,   m.z,v.z); v.w=fmaf(sc,   m.w,v.w);
            m = R[8]; v.x=fmaf(ss,   m.x,v.x); v.y=fmaf(ss,   m.y,v.y); v.z=fmaf(ss,   m.z,v.z); v.w=fmaf(ss,   m.w,v.w);

            o.x = fmaf(w, v.x, o.x);
            o.y = fmaf(w, v.y, o.y);
            o.z = fmaf(w, v.z, o.z);
            o.w = fmaf(w, v.w, o.w);
        }

        out[base + pp * TPB] = o;
    }
}

// ---------------------------------------------------------------------------
extern "C" void kernel_launch(void* const* d_in, const int* in_sizes, int n_in,
                              void* d_out, int out_size)
{
    const float* xyzt   = (const float*)d_in[0];
    const float* Wg     = (const float*)d_in[1];
    const float* bg     = (const float*)d_in[2];
    const float* proj   = (const float*)d_in[3];
    const float* center = (const float*)d_in[4];
    const float* tb1    = (const float*)d_in[5];
    const float* tb2    = (const float*)d_in[6];
    const float* W1     = (const float*)d_in[7];
    const float* Wf     = (const float*)d_in[8];
    const float* bf     = (const float*)d_in[9];

    moe_fused_kernel<<<NBLK, TPB>>>((const float4*)xyzt, Wg, bg, proj, center,
                                    tb1, tb2, W1, Wf, bf, (float4*)d_out);
}